// round 6
// baseline (speedup 1.0000x reference)
#include <cuda_runtime.h>
#include <math.h>

#define NN 4096
#define EE 65536
#define CDIV(a,b) (((a)+(b)-1)/(b))

// ---- static scratch ----
constexpr int O_BCOL=0;
constexpr int O_AP0 =O_BCOL+4096*820;
constexpr int O_AP1 =O_AP0+820*820;
constexpr int O_AP2 =O_AP1+164*164;
constexpr int O_AP3 =O_AP2+33*33;
constexpr int O_AP4 =O_AP3+7*7;
constexpr int O_NA  =O_AP4+2*2;
constexpr int O_P   =O_NA+4096*140;
constexpr int O_Q   =O_P+4096*128;
constexpr int O_ACC =O_Q+4096*128;
constexpr int O_H1  =O_ACC+4096*128;
constexpr int O_Z   =O_H1+4096*128;
constexpr int O_Y   =O_Z+4096*128;
constexpr int O_X0  =O_Y+4096*128;
constexpr int O_XS1 =O_X0+4096*128;
constexpr int O_XS2 =O_XS1+820*128;
constexpr int O_XS3 =O_XS2+164*128;
constexpr int O_XS4 =O_XS3+33*128;
constexpr int O_XP  =O_XS4+7*128;
constexpr int O_XBOT=O_XP+820*128;
constexpr int O_XA  =O_XBOT+2*128;
constexpr int O_XB  =O_XA+4096*128;
constexpr int O_UNET=O_XB+820*128;
constexpr int O_F   =O_UNET+4096*128;
constexpr int O_CAT =O_F+4096*4;
constexpr int O_Z4  =O_CAT+4096*256;
constexpr int O_Y4  =O_Z4+4096*4;
constexpr int O_SC  =O_Y4+4096*4;
constexpr int O_SV  =O_SC+4096;
constexpr int O_PD  =O_SV+1032;
constexpr int O_DI2 =O_PD+1032;
constexpr int O_DI1 =O_DI2+4096;
constexpr int O_CF  =O_DI1+4096;
constexpr int O_PN  =O_CF+4096;
constexpr int BUFSZ =O_PN+8;
__device__ float g_buf[BUFSZ];

constexpr int I_PTR=0, I_COL=4100, I_CUR=I_COL+EE, I_CNT=I_CUR+4096,
              I_PERM=I_CNT+4096, I_POS=I_PERM+1032, IBUFSZ=I_POS+4096;
__device__ int g_ibuf[IBUFSZ];

// ---- kernels ----
__global__ void k_zero(float*p,int n){int i=blockIdx.x*blockDim.x+threadIdx.x;if(i<n)p[i]=0.f;}
__global__ void k_iset(int*p,int n,int v){int i=blockIdx.x*blockDim.x+threadIdx.x;if(i<n)p[i]=v;}
__global__ void k_icopy(int*d,const int*s,int n){int i=blockIdx.x*blockDim.x+threadIdx.x;if(i<n)d[i]=s[i];}
__global__ void k_copy(float*d,const float*s,int n){int i=blockIdx.x*blockDim.x+threadIdx.x;if(i<n)d[i]=s[i];}

__global__ void k_count(const int*dst,int*cnt){int e=blockIdx.x*blockDim.x+threadIdx.x;if(e<EE)atomicAdd(&cnt[dst[e]],1);}
__global__ void k_scan(const int*cnt,int*ptr){
    __shared__ int s[NN]; int tid=threadIdx.x;
    #pragma unroll
    for(int j=0;j<4;j++)s[tid+j*1024]=cnt[tid+j*1024];
    __syncthreads();
    for(int off=1;off<NN;off<<=1){
        int t[4];
        #pragma unroll
        for(int j=0;j<4;j++){int i=tid+j*1024;t[j]=(i>=off)?s[i-off]:0;}
        __syncthreads();
        #pragma unroll
        for(int j=0;j<4;j++){int i=tid+j*1024;s[i]+=t[j];}
        __syncthreads();
    }
    #pragma unroll
    for(int j=0;j<4;j++){int i=tid+j*1024;ptr[i+1]=s[i];}
    if(tid==0)ptr[0]=0;
}
__global__ void k_fillcsr(const int*src,const int*dst,int*cur,int*col){
    int e=blockIdx.x*blockDim.x+threadIdx.x;
    if(e<EE){int d=dst[e];int p=atomicAdd(&cur[d],1);col[p]=src[e];}
}
__global__ void k_dinv(const int*cnt,float*d2,float*d1,float*cf){
    int i=blockIdx.x*blockDim.x+threadIdx.x;
    if(i<NN){float c=(float)cnt[i];d2[i]=rsqrtf(c+2.f);d1[i]=rsqrtf(c+1.f);cf[i]=c;}
}
__global__ void k_pnorm(const float*pw,float*pn){
    __shared__ float r[128]; int tid=threadIdx.x;
    for(int l=0;l<5;l++){
        float v=pw[l*128+tid];r[tid]=v*v;__syncthreads();
        for(int s=64;s>0;s>>=1){if(tid<s)r[tid]+=r[tid+s];__syncthreads();}
        if(tid==0)pn[l]=sqrtf(r[0]);
        __syncthreads();
    }
}
__global__ void k_na(const float*F,const float*mn,const float*h,float*na){
    int i=blockIdx.x*blockDim.x+threadIdx.x;
    if(i<NN*140){int n=i/140,c=i-n*140;
        na[i]=(c<4)?F[n*4+c]:(c<12?mn[n*8+(c-4)]:h[n*128+(c-12)]);}
}
// C[M,N]=A@B with optional row-scale rs, bias, relu. 64x64 tile, 4x4/thread.
__global__ void k_gemm(const float*__restrict__ A,const float*__restrict__ B,
                       float*__restrict__ C,int M,int N,int K,
                       const float*__restrict__ rs,const float*__restrict__ bias,int relu){
    __shared__ float As[16][65], Bs[16][64];
    int tx=threadIdx.x,ty=threadIdx.y,tid=ty*16+tx;
    int m0=blockIdx.y*64,n0=blockIdx.x*64;
    float acc[4][4]={};
    for(int k0=0;k0<K;k0+=16){
        #pragma unroll
        for(int l=0;l<4;l++){int lin=tid+l*256;int m=lin>>4,kk=lin&15;
            int gm=m0+m,gk=k0+kk;
            As[kk][m]=(gm<M&&gk<K)?A[gm*K+gk]:0.f;}
        #pragma unroll
        for(int l=0;l<4;l++){int lin=tid+l*256;int kk=lin>>6,n=lin&63;
            int gk=k0+kk,gn=n0+n;
            Bs[kk][n]=(gk<K&&gn<N)?B[gk*N+gn]:0.f;}
        __syncthreads();
        #pragma unroll
        for(int kk=0;kk<16;kk++){
            float a[4],b[4];
            #pragma unroll
            for(int i=0;i<4;i++)a[i]=As[kk][ty*4+i];
            #pragma unroll
            for(int j=0;j<4;j++)b[j]=Bs[kk][tx*4+j];
            #pragma unroll
            for(int i=0;i<4;i++)
                #pragma unroll
                for(int j=0;j<4;j++)acc[i][j]+=a[i]*b[j];
        }
        __syncthreads();
    }
    #pragma unroll
    for(int i=0;i<4;i++){
        int r=m0+ty*4+i; if(r>=M)continue;
        float sc=rs?rs[r]:1.f;
        #pragma unroll
        for(int j=0;j<4;j++){
            int c=n0+tx*4+j; if(c>=N)continue;
            float v=acc[i][j]*sc;
            if(bias)v+=bias[c];
            if(relu)v=fmaxf(v,0.f);
            C[r*N+c]=v;
        }
    }
}
__global__ void k_msg(const int*__restrict__ src,const int*__restrict__ dst,
                      const float*__restrict__ me,const float*__restrict__ Wm,
                      const float*__restrict__ Q,float*acc){
    int e=blockIdx.x,h=threadIdx.x;
    int s=src[e],d=dst[e];
    const float*Wb=Wm+280*128;
    float v=Q[s*128+h]+me[e*4]*Wb[h]+me[e*4+1]*Wb[128+h]+me[e*4+2]*Wb[256+h]+me[e*4+3]*Wb[384+h];
    atomicAdd(&acc[d*128+h],v);
}
__global__ void k_h1(const float*acc,const float*P,const float*bm,const float*cf,float*h1){
    int i=blockIdx.x*blockDim.x+threadIdx.x;
    if(i<NN*128){int n=i>>7,h=i&127;h1[i]=fmaxf(acc[i]+cf[n]*(P[i]+bm[h]),0.f);}
}
__global__ void k_spmm128(const int*__restrict__ src,const int*__restrict__ dst,
                          const float*__restrict__ z,float*y){
    int e=blockIdx.x,h=threadIdx.x;
    atomicAdd(&y[dst[e]*128+h],z[src[e]*128+h]);
}
__global__ void k_spmm4(const int*__restrict__ src,const int*__restrict__ dst,
                        const float*__restrict__ z,float*y){
    int i=blockIdx.x*blockDim.x+threadIdx.x;
    if(i<EE*4){int e=i>>2,f=i&3;atomicAdd(&y[dst[e]*4+f],z[src[e]*4+f]);}
}
__global__ void k_gcnfin(float*out,const float*y,const float*z,const float*dinv,
                         const float*bias,float fill,int relu,int total,int W){
    int i=blockIdx.x*blockDim.x+threadIdx.x;
    if(i<total){int n=i/W,c=i-n*W;
        float v=dinv[n]*(y[i]+fill*z[i])+bias[c];
        out[i]=relu?fmaxf(v,0.f):v;}
}
__global__ void k_score(const float*x,const float*w,const float*pn,int l,float*sc){
    __shared__ float r[128]; int n=blockIdx.x,tid=threadIdx.x;
    r[tid]=x[n*128+tid]*w[tid];__syncthreads();
    for(int s=64;s>0;s>>=1){if(tid<s)r[tid]+=r[tid+s];__syncthreads();}
    if(tid==0)sc[n]=tanhf(r[0]/pn[l]);
}
// full bitonic sort: desc by value, ties -> lower index (matches lax.top_k)
__global__ void k_topk(const float*sc,int n,int pad,int k,int*perm,float*sv){
    __shared__ float v[4096]; __shared__ int id[4096];
    int tid=threadIdx.x,bs=blockDim.x;
    for(int i=tid;i<pad;i+=bs){v[i]=(i<n)?sc[i]:-3.4e38f;id[i]=(i<n)?i:0x7fffffff;}
    __syncthreads();
    for(int ks=2;ks<=pad;ks<<=1){
        for(int j=ks>>1;j>0;j>>=1){
            for(int i=tid;i<pad;i+=bs){
                int ixj=i^j;
                if(ixj>i){
                    bool up=((i&ks)==0);
                    float va=v[ixj],vb=v[i];int ia=id[ixj],ib=id[i];
                    bool pre=(va>vb)||(va==vb&&ia<ib);
                    if(pre==up){v[ixj]=vb;v[i]=va;id[ixj]=ib;id[i]=ia;}
                }
            }
            __syncthreads();
        }
    }
    for(int i=tid;i<k;i+=bs){perm[i]=id[i];sv[i]=v[i];}
}
__global__ void k_gather(const float*x,const int*perm,const float*sv,float*xp,int k){
    int i=blockIdx.x*blockDim.x+threadIdx.x;
    if(i<k*128){int a=i>>7,h=i&127;xp[i]=x[perm[a]*128+h]*sv[a];}
}
__global__ void k_posset(const int*perm,int*pos,float*bcol){
    int b=blockIdx.x*blockDim.x+threadIdx.x;
    if(b<820){int p=perm[b];pos[p]=b;bcol[p*820+b]=1.f;}
}
__global__ void k_bcol(const int*src,const int*dst,const int*pos,float*bcol){
    int e=blockIdx.x*blockDim.x+threadIdx.x;
    if(e<EE){int s=src[e],d=dst[e];
        if(s!=d){int b=pos[s];if(b>=0)atomicAdd(&bcol[d*820+b],1.f);}}
}
__global__ void k_ap0(const int*__restrict__ perm,const int*__restrict__ ptr,
                      const int*__restrict__ col,const float*__restrict__ bcol,float*ap){
    int a=blockIdx.x;int pa=perm[a];
    __shared__ float row[820];
    for(int b=threadIdx.x;b<820;b+=blockDim.x)row[b]=bcol[pa*820+b];
    __syncthreads();
    int beg=ptr[pa],end=ptr[pa+1];
    for(int idx=beg;idx<end;idx++){
        int kk=col[idx];
        if(kk==pa)continue;
        for(int b=threadIdx.x;b<820;b+=blockDim.x)row[b]+=bcol[kk*820+b];
        __syncthreads();
    }
    for(int b=threadIdx.x;b<820;b+=blockDim.x)ap[a*820+b]=(b==a)?0.f:row[b];
}
__global__ void k_augres(const float*__restrict__ Ap,int n,const int*__restrict__ perm,
                         int m,float*out){
    int i=blockIdx.x*blockDim.x+threadIdx.x;
    if(i>=m*m)return;
    int a=i/m,b=i-a*m;int pa=perm[a],pb=perm[b];
    float s=0.f;
    for(int kk=0;kk<n;kk++){
        float l=(kk==pa)?1.f:Ap[pa*n+kk];
        float r=(kk==pb)?1.f:Ap[kk*n+pb];
        s+=l*r;
    }
    out[i]=(a==b)?0.f:s;
}
__global__ void k_rowdinv(const float*Ap,int m,float*pd){
    int a=blockIdx.x*blockDim.x+threadIdx.x;
    if(a<m){float s=0.f;for(int b=0;b<m;b++)s+=Ap[a*m+b];pd[a]=rsqrtf(s+2.f);}
}
__global__ void k_scatup(float*tmp,const float*x,const int*perm,int k){
    int i=blockIdx.x*blockDim.x+threadIdx.x;
    if(i<k*128){int a=i>>7,h=i&127;tmp[perm[a]*128+h]+=x[i];}
}
__global__ void k_cat(const float*h1,const float*un,float*cat){
    int i=blockIdx.x*blockDim.x+threadIdx.x;
    if(i<NN*128){int n=i>>7,h=i&127;cat[n*256+h]=h1[i];cat[n*256+128+h]=fmaxf(un[i],0.f);}
}
__global__ void k_fout(const float*y4,const float*z4,const float*d1,const float*bout,
                       float*Fb,float*out,int t){
    int i=blockIdx.x*blockDim.x+threadIdx.x;
    if(i<NN*4){int n=i>>2,f=i&3;
        float v=d1[n]*(y4[i]+z4[i])+bout[f];
        Fb[i]=v;out[n*8+t*4+f]=v;}
}

// ---- host ----
static void gemm(const float*A,const float*B,float*C,int M,int N,int K,
                 const float*rs,const float*bias,int relu){
    dim3 b(16,16),g(CDIV(N,64),CDIV(M,64));
    k_gemm<<<g,b>>>(A,B,C,M,N,K,rs,bias,relu);
}
#define Z256(p,n) k_zero<<<CDIV((n),256),256>>>((p),(n))

extern "C" void kernel_launch(void* const* d_in, const int* in_sizes, int n_in,
                              void* d_out, int out_size){
    const float*F0 =(const float*)d_in[0];
    const float*mn =(const float*)d_in[1];
    const float*me =(const float*)d_in[2];
    const float*Wm =(const float*)d_in[3];
    const float*bm =(const float*)d_in[4];
    const float*Wd0=(const float*)d_in[5];
    const float*bd0=(const float*)d_in[6];
    const float*Wd =(const float*)d_in[7];
    const float*bd =(const float*)d_in[8];
    const float*pw =(const float*)d_in[9];
    const float*Wu =(const float*)d_in[10];
    const float*bu =(const float*)d_in[11];
    const float*Wo =(const float*)d_in[12];
    const float*bo =(const float*)d_in[13];
    const int*ei   =(const int*)d_in[14];
    const int*src=ei,*dst=ei+EE;
    float*out=(float*)d_out;

    float*buf;int*ib;
    cudaGetSymbolAddress((void**)&buf,g_buf);
    cudaGetSymbolAddress((void**)&ib,g_ibuf);

    const int NS[6]={4096,820,164,33,7,2};
    const int KL[5]={820,164,33,7,2};
    const int POFF[5]={0,820,984,1017,1024};
    const int PAD[5]={4096,1024,256,64,8};
    float* AP[5]={buf+O_AP0,buf+O_AP1,buf+O_AP2,buf+O_AP3,buf+O_AP4};
    float* XL[6]={buf+O_X0,buf+O_XS1,buf+O_XS2,buf+O_XS3,buf+O_XS4,buf+O_XBOT};
    float*P=buf+O_P,*Q=buf+O_Q,*ACC=buf+O_ACC,*H1=buf+O_H1,*Z=buf+O_Z,*Y=buf+O_Y;
    float*NA=buf+O_NA,*XP=buf+O_XP,*XA=buf+O_XA,*XB=buf+O_XB,*UNET=buf+O_UNET;
    float*FB=buf+O_F,*CAT=buf+O_CAT,*Z4=buf+O_Z4,*Y4=buf+O_Y4,*SC=buf+O_SC;
    float*SV=buf+O_SV,*PD=buf+O_PD,*D2=buf+O_DI2,*D1=buf+O_DI1,*CF=buf+O_CF,*PN=buf+O_PN;
    int*PTR=ib+I_PTR,*COL=ib+I_COL,*CUR=ib+I_CUR,*CNT=ib+I_CNT,*PERM=ib+I_PERM,*POS=ib+I_POS;

    // one-time setup
    Z256(UNET,NN*128);                       // h = 0 at t=0
    k_iset<<<CDIV(NN,256),256>>>(CNT,NN,0);
    k_count<<<CDIV(EE,256),256>>>(dst,CNT);
    k_scan<<<1,1024>>>(CNT,PTR);
    k_icopy<<<CDIV(NN,256),256>>>(CUR,PTR,NN);
    k_fillcsr<<<CDIV(EE,256),256>>>(src,dst,CUR,COL);
    k_dinv<<<CDIV(NN,256),256>>>(CNT,D2,D1,CF);
    k_pnorm<<<1,128>>>(pw,PN);

    for(int t=0;t<2;t++){
        const float*Fc=(t==0)?F0:FB;
        // message passing -> h1
        k_na<<<CDIV(NN*140,256),256>>>(Fc,mn,UNET,NA);
        gemm(NA,Wm,P,NN,128,140,0,0,0);
        gemm(NA,Wm+140*128,Q,NN,128,140,0,0,0);
        Z256(ACC,NN*128);
        k_msg<<<EE,128>>>(src,dst,me,Wm,Q,ACC);
        k_h1<<<CDIV(NN*128,256),256>>>(ACC,P,bm,CF,H1);
        // unet down-0 gcn (fill=2, relu)
        gemm(H1,Wd0,Z,NN,128,128,D2,0,0);
        Z256(Y,NN*128);
        k_spmm128<<<EE,128>>>(src,dst,Z,Y);
        k_gcnfin<<<CDIV(NN*128,256),256>>>(XL[0],Y,Z,D2,bd0,2.f,1,NN*128,128);
        // down levels
        for(int i=0;i<5;i++){
            int n=NS[i],k=KL[i];
            k_score<<<n,128>>>(XL[i],pw+i*128,PN,i,SC);
            k_topk<<<1,1024>>>(SC,n,PAD[i],k,PERM+POFF[i],SV+POFF[i]);
            if(i==0){
                Z256(buf+O_BCOL,4096*820);
                k_iset<<<CDIV(NN,256),256>>>(POS,NN,-1);
                k_posset<<<CDIV(820,256),256>>>(PERM,POS,buf+O_BCOL);
                k_bcol<<<CDIV(EE,256),256>>>(src,dst,POS,buf+O_BCOL);
                k_ap0<<<820,256>>>(PERM,PTR,COL,buf+O_BCOL,AP[0]);
            }else{
                k_augres<<<CDIV(k*k,256),256>>>(AP[i-1],n,PERM+POFF[i],k,AP[i]);
            }
            k_rowdinv<<<CDIV(k,64),64>>>(AP[i],k,PD+POFF[i]);
            k_gather<<<CDIV(k*128,256),256>>>(XL[i],PERM+POFF[i],SV+POFF[i],XP,k);
            gemm(XP,Wd+i*16384,Z,k,128,128,PD+POFF[i],0,0);
            gemm(AP[i],Z,Y,k,128,k,0,0,0);
            k_gcnfin<<<CDIV(k*128,256),256>>>(XL[i+1],Y,Z,PD+POFF[i],bd+i*128,2.f,1,k*128,128);
        }
        // up levels
        float*xin=XL[5];
        for(int i=0;i<5;i++){
            int j=4-i;
            if(j>0){
                int nj=NS[j],kj=KL[j];
                k_copy<<<CDIV(nj*128,256),256>>>(XA,XL[j],nj*128);
                k_scatup<<<CDIV(kj*128,256),256>>>(XA,xin,PERM+POFF[j],kj);
                gemm(XA,Wu+i*16384,Z,nj,128,128,PD+POFF[j-1],0,0);
                gemm(AP[j-1],Z,Y,nj,128,nj,0,0,0);
                float*xo=(i%2==0)?XB:XP;
                k_gcnfin<<<CDIV(nj*128,256),256>>>(xo,Y,Z,PD+POFF[j-1],bu+i*128,2.f,1,nj*128,128);
                xin=xo;
            }else{
                k_copy<<<CDIV(NN*128,256),256>>>(XA,XL[0],NN*128);
                k_scatup<<<CDIV(820*128,256),256>>>(XA,xin,PERM,820);
                gemm(XA,Wu+4*16384,Z,NN,128,128,D2,0,0);
                Z256(Y,NN*128);
                k_spmm128<<<EE,128>>>(src,dst,Z,Y);
                k_gcnfin<<<CDIV(NN*128,256),256>>>(UNET,Y,Z,D2,bu+4*128,2.f,0,NN*128,128);
            }
        }
        // output gcn (fill=1)
        k_cat<<<CDIV(NN*128,256),256>>>(H1,UNET,CAT);
        gemm(CAT,Wo,Z4,NN,4,256,D1,0,0);
        Z256(Y4,NN*4);
        k_spmm4<<<CDIV(EE*4,256),256>>>(src,dst,Z4,Y4);
        k_fout<<<CDIV(NN*4,256),256>>>(Y4,Z4,D1,bo,FB,out,t);
    }
}

// round 7
// speedup vs baseline: 1.3955x; 1.3955x over previous
#include <cuda_runtime.h>
#include <math.h>

#define NN 4096
#define EE 65536
#define CDIV(a,b) (((a)+(b)-1)/(b))

// ---- static scratch (floats) ----
constexpr int O_AP0 =0;
constexpr int O_AP1 =O_AP0+820*820;
constexpr int O_AP2 =O_AP1+164*164;
constexpr int O_AP3 =O_AP2+33*33;
constexpr int O_AP4 =O_AP3+7*7;
constexpr int O_L   =O_AP4+2*2;
constexpr int O_R   =O_L+164*820;
constexpr int O_NA  =O_R+820*164;
constexpr int O_P   =O_NA+4096*140;
constexpr int O_Q   =O_P+4096*128;
constexpr int O_H1  =O_Q+4096*128;
constexpr int O_Z   =O_H1+4096*128;
constexpr int O_X0  =O_Z+4096*128;
constexpr int O_XS1 =O_X0+4096*128;
constexpr int O_XS2 =O_XS1+820*128;
constexpr int O_XS3 =O_XS2+164*128;
constexpr int O_XS4 =O_XS3+33*128;
constexpr int O_XBOT=O_XS4+7*128;
constexpr int O_XP  =O_XBOT+2*128;
constexpr int O_XA  =O_XP+820*128;
constexpr int O_XB  =O_XA+4096*128;
constexpr int O_UNET=O_XB+820*128;
constexpr int O_F   =O_UNET+4096*128;
constexpr int O_CAT =O_F+4096*4;
constexpr int O_Z4  =O_CAT+4096*256;
constexpr int O_SC  =O_Z4+4096*4;
constexpr int O_SV  =O_SC+4096;
constexpr int O_PD  =O_SV+1032;
constexpr int O_DI2 =O_PD+1032;
constexpr int O_DI1 =O_DI2+4096;
constexpr int O_CF  =O_DI1+4096;
constexpr int O_PN  =O_CF+4096;
constexpr int BUFSZ =O_PN+8;
__device__ float g_buf[BUFSZ];

constexpr int I_PTR=0, I_COL=4100, I_EID=I_COL+EE, I_CUR=I_EID+EE,
              I_CNT=I_CUR+4096, I_PERM=I_CNT+4096, I_POS=I_PERM+1032,
              IBUFSZ=I_POS+4096;
__device__ int g_ibuf[IBUFSZ];

// ---- kernels ----
__global__ void k_zero(float*p,int n){int i=blockIdx.x*blockDim.x+threadIdx.x;if(i<n)p[i]=0.f;}
__global__ void k_iset(int*p,int n,int v){int i=blockIdx.x*blockDim.x+threadIdx.x;if(i<n)p[i]=v;}
__global__ void k_icopy(int*d,const int*s,int n){int i=blockIdx.x*blockDim.x+threadIdx.x;if(i<n)d[i]=s[i];}
__global__ void k_copy(float*d,const float*s,int n){int i=blockIdx.x*blockDim.x+threadIdx.x;if(i<n)d[i]=s[i];}

__global__ void k_count(const int*dst,int*cnt){int e=blockIdx.x*blockDim.x+threadIdx.x;if(e<EE)atomicAdd(&cnt[dst[e]],1);}
__global__ void k_scan(const int*cnt,int*ptr){
    __shared__ int s[NN]; int tid=threadIdx.x;
    #pragma unroll
    for(int j=0;j<4;j++)s[tid+j*1024]=cnt[tid+j*1024];
    __syncthreads();
    for(int off=1;off<NN;off<<=1){
        int t[4];
        #pragma unroll
        for(int j=0;j<4;j++){int i=tid+j*1024;t[j]=(i>=off)?s[i-off]:0;}
        __syncthreads();
        #pragma unroll
        for(int j=0;j<4;j++){int i=tid+j*1024;s[i]+=t[j];}
        __syncthreads();
    }
    #pragma unroll
    for(int j=0;j<4;j++){int i=tid+j*1024;ptr[i+1]=s[i];}
    if(tid==0)ptr[0]=0;
}
__global__ void k_fillcsr(const int*src,const int*dst,int*cur,int*col,int*eid){
    int e=blockIdx.x*blockDim.x+threadIdx.x;
    if(e<EE){int d=dst[e];int p=atomicAdd(&cur[d],1);col[p]=src[e];eid[p]=e;}
}
__global__ void k_dinv(const int*cnt,float*d2,float*d1,float*cf){
    int i=blockIdx.x*blockDim.x+threadIdx.x;
    if(i<NN){float c=(float)cnt[i];d2[i]=rsqrtf(c+2.f);d1[i]=rsqrtf(c+1.f);cf[i]=c;}
}
__global__ void k_pnorm(const float*pw,float*pn){
    __shared__ float r[128]; int tid=threadIdx.x;
    for(int l=0;l<5;l++){
        float v=pw[l*128+tid];r[tid]=v*v;__syncthreads();
        for(int s=64;s>0;s>>=1){if(tid<s)r[tid]+=r[tid+s];__syncthreads();}
        if(tid==0)pn[l]=sqrtf(r[0]);
        __syncthreads();
    }
}
__global__ void k_na(const float*F,const float*mn,const float*h,float*na){
    int i=blockIdx.x*blockDim.x+threadIdx.x;
    if(i<NN*140){int n=i/140,c=i-n*140;
        na[i]=(c<4)?F[n*4+c]:(c<12?mn[n*8+(c-4)]:h[n*128+(c-12)]);}
}
// C[M,N] = rs ⊙ (A@B + fill*D) + bias, relu.  64x64 tile, 4x4/thread.
__global__ void k_gemm(const float*__restrict__ A,const float*__restrict__ B,
                       float*__restrict__ C,int M,int N,int K,
                       const float*__restrict__ rs,const float*__restrict__ bias,int relu,
                       const float*__restrict__ Dm,float fill){
    __shared__ float As[16][65], Bs[16][64];
    int tx=threadIdx.x,ty=threadIdx.y,tid=ty*16+tx;
    int m0=blockIdx.y*64,n0=blockIdx.x*64;
    float acc[4][4]={};
    for(int k0=0;k0<K;k0+=16){
        #pragma unroll
        for(int l=0;l<4;l++){int lin=tid+l*256;int m=lin>>4,kk=lin&15;
            int gm=m0+m,gk=k0+kk;
            As[kk][m]=(gm<M&&gk<K)?A[gm*K+gk]:0.f;}
        #pragma unroll
        for(int l=0;l<4;l++){int lin=tid+l*256;int kk=lin>>6,n=lin&63;
            int gk=k0+kk,gn=n0+n;
            Bs[kk][n]=(gk<K&&gn<N)?B[gk*N+gn]:0.f;}
        __syncthreads();
        #pragma unroll
        for(int kk=0;kk<16;kk++){
            float a[4],b[4];
            #pragma unroll
            for(int i=0;i<4;i++)a[i]=As[kk][ty*4+i];
            #pragma unroll
            for(int j=0;j<4;j++)b[j]=Bs[kk][tx*4+j];
            #pragma unroll
            for(int i=0;i<4;i++)
                #pragma unroll
                for(int j=0;j<4;j++)acc[i][j]+=a[i]*b[j];
        }
        __syncthreads();
    }
    #pragma unroll
    for(int i=0;i<4;i++){
        int r=m0+ty*4+i; if(r>=M)continue;
        float sc=rs?rs[r]:1.f;
        #pragma unroll
        for(int j=0;j<4;j++){
            int c=n0+tx*4+j; if(c>=N)continue;
            float v=acc[i][j];
            if(Dm)v+=fill*Dm[r*N+c];
            v*=sc;
            if(bias)v+=bias[c];
            if(relu)v=fmaxf(v,0.f);
            C[r*N+c]=v;
        }
    }
}
// fused message aggregation + relu(h1). block per dst node, 128 threads.
__global__ void k_h1m(const int*__restrict__ ptr,const int*__restrict__ col,
                      const int*__restrict__ eid,const float*__restrict__ me,
                      const float*__restrict__ Wm,const float*__restrict__ Q,
                      const float*__restrict__ P,const float*__restrict__ bm,
                      const float*__restrict__ cf,float*h1){
    __shared__ float wb[512];
    int d=blockIdx.x,h=threadIdx.x;
    const float*Wb=Wm+280*128;
    for(int i=h;i<512;i+=128)wb[i]=Wb[i];
    __syncthreads();
    float s=0.f;
    int e0=ptr[d],e1=ptr[d+1];
    for(int i=e0;i<e1;i++){
        int c=col[i],e=eid[i];
        s+=Q[c*128+h]+me[e*4]*wb[h]+me[e*4+1]*wb[128+h]+me[e*4+2]*wb[256+h]+me[e*4+3]*wb[384+h];
    }
    h1[d*128+h]=fmaxf(s+cf[d]*(P[d*128+h]+bm[h]),0.f);
}
// fused CSR spmm + gcn epilogue: out[d,h]=dinv[d]*(sum_nb z + fill*z[d,h])+bias[h]
__global__ void k_spmmgcn(const int*__restrict__ ptr,const int*__restrict__ col,
                          const float*__restrict__ z,const float*__restrict__ dinv,
                          const float*__restrict__ bias,float fill,int relu,float*out){
    int d=blockIdx.x,h=threadIdx.x;
    float s=0.f;
    int e0=ptr[d],e1=ptr[d+1];
    for(int i=e0;i<e1;i++)s+=z[col[i]*128+h];
    float v=dinv[d]*(s+fill*z[d*128+h])+bias[h];
    out[d*128+h]=relu?fmaxf(v,0.f):v;
}
__global__ void k_score(const float*x,const float*w,const float*pn,int l,float*sc){
    __shared__ float r[128]; int n=blockIdx.x,tid=threadIdx.x;
    r[tid]=x[n*128+tid]*w[tid];__syncthreads();
    for(int s=64;s>0;s>>=1){if(tid<s)r[tid]+=r[tid+s];__syncthreads();}
    if(tid==0)sc[n]=tanhf(r[0]/pn[l]);
}
// bitonic: desc by value, ties -> lower index (matches lax.top_k)
__global__ void k_topk(const float*sc,int n,int pad,int k,int*perm,float*sv){
    __shared__ float v[4096]; __shared__ int id[4096];
    int tid=threadIdx.x,bs=blockDim.x;
    for(int i=tid;i<pad;i+=bs){v[i]=(i<n)?sc[i]:-3.4e38f;id[i]=(i<n)?i:0x7fffffff;}
    __syncthreads();
    for(int ks=2;ks<=pad;ks<<=1){
        for(int j=ks>>1;j>0;j>>=1){
            for(int i=tid;i<pad;i+=bs){
                int ixj=i^j;
                if(ixj>i){
                    bool up=((i&ks)==0);
                    float va=v[ixj],vb=v[i];int ia=id[ixj],ib=id[i];
                    bool pre=(va>vb)||(va==vb&&ia<ib);
                    if(pre==up){v[ixj]=vb;v[i]=va;id[ixj]=ib;id[i]=ia;}
                }
            }
            __syncthreads();
        }
    }
    for(int i=tid;i<k;i+=bs){perm[i]=id[i];sv[i]=v[i];}
}
__global__ void k_gather(const float*x,const int*perm,const float*sv,float*xp,int k){
    int i=blockIdx.x*blockDim.x+threadIdx.x;
    if(i<k*128){int a=i>>7,h=i&127;xp[i]=x[perm[a]*128+h]*sv[a];}
}
__global__ void k_posset(const int*perm,int*pos){
    int b=blockIdx.x*blockDim.x+threadIdx.x;
    if(b<820)pos[perm[b]]=b;
}
// AP0[a,b] = 2*cnt(pa,pb) + sum_{k != pa, k != pb} cnt(pa,k)*cnt(k,pb); diag zeroed later
__global__ void k_ap0n(const int*__restrict__ perm,const int*__restrict__ ptr,
                       const int*__restrict__ col,const int*__restrict__ pos,float*ap){
    int a=blockIdx.x;int pa=perm[a];
    int beg=ptr[pa],end=ptr[pa+1];
    for(int i1=beg;i1<end;i1++){
        int c1=col[i1];
        if(c1==pa)continue;
        if(threadIdx.x==0){int b=pos[c1];if(b>=0)atomicAdd(&ap[a*820+b],2.f);}
        int b2=ptr[c1],e2=ptr[c1+1];
        for(int i2=b2+threadIdx.x;i2<e2;i2+=blockDim.x){
            int c2=col[i2];
            if(c2==c1)continue;
            int b=pos[c2];
            if(b>=0)atomicAdd(&ap[a*820+b],1.f);
        }
    }
}
__global__ void k_zdiag(float*ap,int m){
    int a=blockIdx.x*blockDim.x+threadIdx.x; if(a<m)ap[a*m+a]=0.f;
}
// L[m x n]: row a = A1[perm[a], :];  R[n x m]: col b = A1[:, perm[b]]
__global__ void k_gL(const float*Ap,int n,const int*perm,int m,float*L){
    int i=blockIdx.x*blockDim.x+threadIdx.x;
    if(i<m*n){int a=i/n,k=i-a*n;int pa=perm[a];L[i]=(k==pa)?1.f:Ap[pa*n+k];}
}
__global__ void k_gR(const float*Ap,int n,const int*perm,int m,float*R){
    int i=blockIdx.x*blockDim.x+threadIdx.x;
    if(i<n*m){int k=i/m,b=i-k*m;int pb=perm[b];R[i]=(k==pb)?1.f:Ap[k*n+pb];}
}
__global__ void k_rowdinv(const float*Ap,int m,float*pd){
    int a=blockIdx.x*blockDim.x+threadIdx.x;
    if(a<m){float s=0.f;for(int b=0;b<m;b++)s+=Ap[a*m+b];pd[a]=rsqrtf(s+2.f);}
}
__global__ void k_scatup(float*tmp,const float*x,const int*perm,int k){
    int i=blockIdx.x*blockDim.x+threadIdx.x;
    if(i<k*128){int a=i>>7,h=i&127;tmp[perm[a]*128+h]+=x[i];}
}
__global__ void k_cat(const float*h1,const float*un,float*cat){
    int i=blockIdx.x*blockDim.x+threadIdx.x;
    if(i<NN*128){int n=i>>7,h=i&127;cat[n*256+h]=h1[i];cat[n*256+128+h]=fmaxf(un[i],0.f);}
}
__global__ void k_fout(const int*__restrict__ ptr,const int*__restrict__ col,
                       const float*__restrict__ z4,const float*__restrict__ d1,
                       const float*__restrict__ bo,float*Fb,float*out,int t){
    int i=blockIdx.x*blockDim.x+threadIdx.x;
    if(i<NN*4){int d=i>>2,f=i&3;
        float s=0.f;
        int e0=ptr[d],e1=ptr[d+1];
        for(int j=e0;j<e1;j++)s+=z4[col[j]*4+f];
        float v=d1[d]*(s+z4[i])+bo[f];
        Fb[i]=v;out[d*8+t*4+f]=v;}
}

// ---- host ----
static void gemm(const float*A,const float*B,float*C,int M,int N,int K,
                 const float*rs,const float*bias,int relu,const float*Dm=0,float fill=0.f){
    dim3 b(16,16),g(CDIV(N,64),CDIV(M,64));
    k_gemm<<<g,b>>>(A,B,C,M,N,K,rs,bias,relu,Dm,fill);
}
#define Z256(p,n) k_zero<<<CDIV((n),256),256>>>((p),(n))

extern "C" void kernel_launch(void* const* d_in, const int* in_sizes, int n_in,
                              void* d_out, int out_size){
    const float*F0 =(const float*)d_in[0];
    const float*mn =(const float*)d_in[1];
    const float*me =(const float*)d_in[2];
    const float*Wm =(const float*)d_in[3];
    const float*bm =(const float*)d_in[4];
    const float*Wd0=(const float*)d_in[5];
    const float*bd0=(const float*)d_in[6];
    const float*Wd =(const float*)d_in[7];
    const float*bd =(const float*)d_in[8];
    const float*pw =(const float*)d_in[9];
    const float*Wu =(const float*)d_in[10];
    const float*bu =(const float*)d_in[11];
    const float*Wo =(const float*)d_in[12];
    const float*bo =(const float*)d_in[13];
    const int*ei   =(const int*)d_in[14];
    const int*src=ei,*dst=ei+EE;
    float*out=(float*)d_out;

    float*buf;int*ib;
    cudaGetSymbolAddress((void**)&buf,g_buf);
    cudaGetSymbolAddress((void**)&ib,g_ibuf);

    const int NS[6]={4096,820,164,33,7,2};
    const int KL[5]={820,164,33,7,2};
    const int POFF[5]={0,820,984,1017,1024};
    const int PAD[5]={4096,1024,256,64,8};
    float* AP[5]={buf+O_AP0,buf+O_AP1,buf+O_AP2,buf+O_AP3,buf+O_AP4};
    float* XL[6]={buf+O_X0,buf+O_XS1,buf+O_XS2,buf+O_XS3,buf+O_XS4,buf+O_XBOT};
    float*P=buf+O_P,*Q=buf+O_Q,*H1=buf+O_H1,*Z=buf+O_Z;
    float*NA=buf+O_NA,*XP=buf+O_XP,*XA=buf+O_XA,*XB=buf+O_XB,*UNET=buf+O_UNET;
    float*FB=buf+O_F,*CAT=buf+O_CAT,*Z4=buf+O_Z4,*SC=buf+O_SC;
    float*SV=buf+O_SV,*PD=buf+O_PD,*D2=buf+O_DI2,*D1=buf+O_DI1,*CF=buf+O_CF,*PN=buf+O_PN;
    float*Lb=buf+O_L,*Rb=buf+O_R;
    int*PTR=ib+I_PTR,*COL=ib+I_COL,*EID=ib+I_EID,*CUR=ib+I_CUR,*CNT=ib+I_CNT,
       *PERM=ib+I_PERM,*POS=ib+I_POS;

    // one-time setup
    Z256(UNET,NN*128);
    k_iset<<<CDIV(NN,256),256>>>(CNT,NN,0);
    k_count<<<CDIV(EE,256),256>>>(dst,CNT);
    k_scan<<<1,1024>>>(CNT,PTR);
    k_icopy<<<CDIV(NN,256),256>>>(CUR,PTR,NN);
    k_fillcsr<<<CDIV(EE,256),256>>>(src,dst,CUR,COL,EID);
    k_dinv<<<CDIV(NN,256),256>>>(CNT,D2,D1,CF);
    k_pnorm<<<1,128>>>(pw,PN);

    for(int t=0;t<2;t++){
        const float*Fc=(t==0)?F0:FB;
        // message passing -> h1
        k_na<<<CDIV(NN*140,256),256>>>(Fc,mn,UNET,NA);
        gemm(NA,Wm,P,NN,128,140,0,0,0);
        gemm(NA,Wm+140*128,Q,NN,128,140,0,0,0);
        k_h1m<<<NN,128>>>(PTR,COL,EID,me,Wm,Q,P,bm,CF,H1);
        // unet down-0 gcn (fill=2, relu)
        gemm(H1,Wd0,Z,NN,128,128,D2,0,0);
        k_spmmgcn<<<NN,128>>>(PTR,COL,Z,D2,bd0,2.f,1,XL[0]);
        // down levels
        for(int i=0;i<5;i++){
            int n=NS[i],k=KL[i];
            k_score<<<n,128>>>(XL[i],pw+i*128,PN,i,SC);
            k_topk<<<1,1024>>>(SC,n,PAD[i],k,PERM+POFF[i],SV+POFF[i]);
            if(i==0){
                Z256(AP[0],820*820);
                k_iset<<<CDIV(NN,256),256>>>(POS,NN,-1);
                k_posset<<<CDIV(820,256),256>>>(PERM,POS);
                k_ap0n<<<820,32>>>(PERM,PTR,COL,POS,AP[0]);
                k_zdiag<<<CDIV(820,256),256>>>(AP[0],820);
            }else{
                k_gL<<<CDIV(k*n,256),256>>>(AP[i-1],n,PERM+POFF[i],k,Lb);
                k_gR<<<CDIV(n*k,256),256>>>(AP[i-1],n,PERM+POFF[i],k,Rb);
                gemm(Lb,Rb,AP[i],k,k,n,0,0,0);
                k_zdiag<<<CDIV(k,64),64>>>(AP[i],k);
            }
            k_rowdinv<<<CDIV(k,64),64>>>(AP[i],k,PD+POFF[i]);
            k_gather<<<CDIV(k*128,256),256>>>(XL[i],PERM+POFF[i],SV+POFF[i],XP,k);
            gemm(XP,Wd+i*16384,Z,k,128,128,PD+POFF[i],0,0);
            gemm(AP[i],Z,XL[i+1],k,128,k,PD+POFF[i],bd+i*128,1,Z,2.f);
        }
        // up levels
        float*xin=XL[5];
        for(int i=0;i<5;i++){
            int j=4-i;
            if(j>0){
                int nj=NS[j],kj=KL[j];
                k_copy<<<CDIV(nj*128,256),256>>>(XA,XL[j],nj*128);
                k_scatup<<<CDIV(kj*128,256),256>>>(XA,xin,PERM+POFF[j],kj);
                gemm(XA,Wu+i*16384,Z,nj,128,128,PD+POFF[j-1],0,0);
                float*xo=(i%2==0)?XB:XP;
                gemm(AP[j-1],Z,xo,nj,128,nj,PD+POFF[j-1],bu+i*128,1,Z,2.f);
                xin=xo;
            }else{
                k_copy<<<CDIV(NN*128,256),256>>>(XA,XL[0],NN*128);
                k_scatup<<<CDIV(820*128,256),256>>>(XA,xin,PERM,820);
                gemm(XA,Wu+4*16384,Z,NN,128,128,D2,0,0);
                k_spmmgcn<<<NN,128>>>(PTR,COL,Z,D2,bu+4*128,2.f,0,UNET);
            }
        }
        // output gcn (fill=1)
        k_cat<<<CDIV(NN*128,256),256>>>(H1,UNET,CAT);
        gemm(CAT,Wo,Z4,NN,4,256,D1,0,0);
        k_fout<<<CDIV(NN*4,256),256>>>(PTR,COL,Z4,D1,bo,FB,out,t);
    }
}